// round 1
// baseline (speedup 1.0000x reference)
#include <cuda_runtime.h>
#include <cuda_bf16.h>
#include <math.h>

// ---------------------------------------------------------------------------
// Problem constants
// ---------------------------------------------------------------------------
#define BB   8
#define LL   1024
#define BL   (BB*LL)          // 8192 tokens
#define QUES 4000
#define EMB  256
#define DM   1024
#define DI   2048
#define NN   16
#define DTR  64
#define KK   4

// ---------------------------------------------------------------------------
// Scratch (static device allocations; no cudaMalloc allowed)
// ---------------------------------------------------------------------------
__device__ float g_item [BL*DM];        // 33.5 MB
__device__ float g_ur   [(size_t)BL*2*DI];  // 134 MB
__device__ float g_ucv  [(size_t)BL*DI];    // 67 MB
__device__ float g_dbl  [BL*96];        // 3 MB
__device__ float g_delta[(size_t)BL*DI];    // 67 MB
__device__ float g_yg   [(size_t)BL*DI];    // 67 MB
__device__ float g_hout [BL*DM];        // 33.5 MB
__device__ float g_lnout[BL*DM];        // 33.5 MB

// ---------------------------------------------------------------------------
// 1) Embedding gather + concat + LayerNorm0  (one block per token)
// ---------------------------------------------------------------------------
__global__ void embed_ln0_kernel(const int* __restrict__ x, const int* __restrict__ qid,
                                 const float* __restrict__ emb, const float* __restrict__ qc,
                                 const float* __restrict__ g, const float* __restrict__ b,
                                 float* __restrict__ item)
{
    int tok = blockIdx.x;
    int t   = threadIdx.x;                 // 256 threads
    int xv  = x[tok];
    int qv  = qid[tok];

    float v[4];
    v[0] = emb[(size_t)xv*EMB + t];                       // j = t       (<256)
    v[1] = qc [(size_t)qv*768 + t];                       // j = 256+t
    v[2] = qc [(size_t)qv*768 + 256 + t];                 // j = 512+t
    v[3] = qc [(size_t)qv*768 + 512 + t];                 // j = 768+t

    float s  = v[0]+v[1]+v[2]+v[3];
    float sq = v[0]*v[0]+v[1]*v[1]+v[2]*v[2]+v[3]*v[3];

    // warp + block reduce
    #pragma unroll
    for (int o = 16; o > 0; o >>= 1) {
        s  += __shfl_xor_sync(0xffffffffu, s,  o);
        sq += __shfl_xor_sync(0xffffffffu, sq, o);
    }
    __shared__ float ws[8], wq[8];
    int lane = t & 31, warp = t >> 5;
    if (lane == 0) { ws[warp] = s; wq[warp] = sq; }
    __syncthreads();
    __shared__ float s_mean, s_rstd;
    if (t == 0) {
        float ts = 0.f, tq = 0.f;
        #pragma unroll
        for (int i = 0; i < 8; i++) { ts += ws[i]; tq += wq[i]; }
        float mean = ts * (1.0f/DM);
        float var  = tq * (1.0f/DM) - mean*mean;
        s_mean = mean;
        s_rstd = rsqrtf(var + 1e-12f);
    }
    __syncthreads();
    float mean = s_mean, rstd = s_rstd;

    #pragma unroll
    for (int i = 0; i < 4; i++) {
        int j = t + i*256;
        item[(size_t)tok*DM + j] = (v[i] - mean) * rstd * g[j] + b[j];
    }
}

// ---------------------------------------------------------------------------
// 2) Residual add + LayerNorm1
// ---------------------------------------------------------------------------
__global__ void add_ln_kernel(const float* __restrict__ a, const float* __restrict__ res,
                              const float* __restrict__ g, const float* __restrict__ b,
                              float* __restrict__ out)
{
    int tok = blockIdx.x;
    int t   = threadIdx.x;                 // 256 threads
    float v[4];
    #pragma unroll
    for (int i = 0; i < 4; i++) {
        int j = t + i*256;
        v[i] = a[(size_t)tok*DM + j] + res[(size_t)tok*DM + j];
    }
    float s  = v[0]+v[1]+v[2]+v[3];
    float sq = v[0]*v[0]+v[1]*v[1]+v[2]*v[2]+v[3]*v[3];
    #pragma unroll
    for (int o = 16; o > 0; o >>= 1) {
        s  += __shfl_xor_sync(0xffffffffu, s,  o);
        sq += __shfl_xor_sync(0xffffffffu, sq, o);
    }
    __shared__ float ws[8], wq[8];
    int lane = t & 31, warp = t >> 5;
    if (lane == 0) { ws[warp] = s; wq[warp] = sq; }
    __syncthreads();
    __shared__ float s_mean, s_rstd;
    if (t == 0) {
        float ts = 0.f, tq = 0.f;
        #pragma unroll
        for (int i = 0; i < 8; i++) { ts += ws[i]; tq += wq[i]; }
        float mean = ts * (1.0f/DM);
        float var  = tq * (1.0f/DM) - mean*mean;
        s_mean = mean;
        s_rstd = rsqrtf(var + 1e-12f);
    }
    __syncthreads();
    float mean = s_mean, rstd = s_rstd;
    #pragma unroll
    for (int i = 0; i < 4; i++) {
        int j = t + i*256;
        out[(size_t)tok*DM + j] = (v[i] - mean) * rstd * g[j] + b[j];
    }
}

// ---------------------------------------------------------------------------
// 3) Generic fp32 GEMM:  C[M,N] = A[M,K] (lda) * B[N,K]^T (ldb)
//    128x128 block tile, BK=16, 256 threads, 8x8 micro-tile.
//    EPI: 0 = none, 1 = bias+softplus, 2 = bias+sigmoid
// ---------------------------------------------------------------------------
template<int EPI>
__global__ __launch_bounds__(256)
void gemm_tn(const float* __restrict__ A, int lda,
             const float* __restrict__ B, int ldb,
             float* __restrict__ C, int ldc,
             int M, int N, int K,
             const float* __restrict__ bias)
{
    __shared__ float As[16][136];
    __shared__ float Bs[16][136];

    int tx = threadIdx.x & 15;
    int ty = threadIdx.x >> 4;
    int m0 = blockIdx.y * 128;
    int n0 = blockIdx.x * 128;

    float acc[8][8];
    #pragma unroll
    for (int i = 0; i < 8; i++)
        #pragma unroll
        for (int j = 0; j < 8; j++) acc[i][j] = 0.f;

    for (int k0 = 0; k0 < K; k0 += 16) {
        #pragma unroll
        for (int i = 0; i < 2; i++) {
            int idx = threadIdx.x + i*256;
            int row = idx >> 2;
            int kq  = (idx & 3) << 2;
            float4 va = make_float4(0.f,0.f,0.f,0.f);
            float4 vb = make_float4(0.f,0.f,0.f,0.f);
            int gm = m0 + row;
            if (gm < M) va = *(const float4*)(A + (size_t)gm*lda + k0 + kq);
            int gn = n0 + row;
            if (gn < N) vb = *(const float4*)(B + (size_t)gn*ldb + k0 + kq);
            As[kq+0][row] = va.x; As[kq+1][row] = va.y;
            As[kq+2][row] = va.z; As[kq+3][row] = va.w;
            Bs[kq+0][row] = vb.x; Bs[kq+1][row] = vb.y;
            Bs[kq+2][row] = vb.z; Bs[kq+3][row] = vb.w;
        }
        __syncthreads();

        #pragma unroll
        for (int kk = 0; kk < 16; kk++) {
            float a[8], bb[8];
            *(float4*)&a[0]  = *(const float4*)&As[kk][ty*8];
            *(float4*)&a[4]  = *(const float4*)&As[kk][ty*8+4];
            *(float4*)&bb[0] = *(const float4*)&Bs[kk][tx*8];
            *(float4*)&bb[4] = *(const float4*)&Bs[kk][tx*8+4];
            #pragma unroll
            for (int i = 0; i < 8; i++)
                #pragma unroll
                for (int j = 0; j < 8; j++)
                    acc[i][j] = fmaf(a[i], bb[j], acc[i][j]);
        }
        __syncthreads();
    }

    #pragma unroll
    for (int i = 0; i < 8; i++) {
        int m = m0 + ty*8 + i;
        if (m >= M) continue;
        #pragma unroll
        for (int j = 0; j < 8; j++) {
            int nn = n0 + tx*8 + j;
            if (nn >= N) continue;
            float v = acc[i][j];
            if (EPI == 1) {                       // bias + softplus
                v += bias[nn];
                v = (v > 20.f) ? v : log1pf(expf(v));
            } else if (EPI == 2) {                // bias + sigmoid
                v += bias[nn];
                v = 1.f / (1.f + expf(-v));
            }
            C[(size_t)m*ldc + nn] = v;
        }
    }
}

// ---------------------------------------------------------------------------
// 4) Depthwise causal conv (K=4) + SiLU. One thread per (b,d), loop over L.
//    input u = g_ur[:, :DI]  (row stride 2*DI)
// ---------------------------------------------------------------------------
__global__ void conv_silu_kernel(const float* __restrict__ ur,
                                 const float* __restrict__ w,
                                 const float* __restrict__ cb,
                                 float* __restrict__ out)
{
    int d = blockIdx.x * 256 + threadIdx.x;  // 0..2047
    int b = blockIdx.y;
    float w0 = w[d*4+0], w1 = w[d*4+1], w2 = w[d*4+2], w3 = w[d*4+3];
    float bias = cb[d];
    float x0 = 0.f, x1 = 0.f, x2 = 0.f;
    size_t rbase = (size_t)b * LL;
    for (int l = 0; l < LL; l++) {
        size_t idx = rbase + l;
        float xc = ur[idx*(2*DI) + d];
        float c  = fmaf(x0, w0, fmaf(x1, w1, fmaf(x2, w2, fmaf(xc, w3, bias))));
        out[idx*DI + d] = c / (1.f + __expf(-c));
        x0 = x1; x1 = x2; x2 = xc;
    }
}

// ---------------------------------------------------------------------------
// 5) Selective scan. One thread per (b, d, n); 16 n-lanes reduced by shfl.
//    Produces y_gated = (scan_y + u*D) * silu(r)
// ---------------------------------------------------------------------------
__global__ void scan_kernel(const float* __restrict__ delta,
                            const float* __restrict__ ucv,
                            const float* __restrict__ dbl,
                            const float* __restrict__ ur,
                            const float* __restrict__ A_log,
                            const float* __restrict__ D_param,
                            float* __restrict__ yg)
{
    int t = threadIdx.x;               // 256 threads: 16 d-lanes x 16 n
    int n = t & 15;
    int d = blockIdx.x * 16 + (t >> 4);
    int b = blockIdx.y;

    float A  = -expf(A_log[d*NN + n]);
    float Dd = D_param[d];
    float h  = 0.f;
    size_t base = (size_t)b * LL;

    for (int l = 0; l < LL; l++) {
        size_t idx = base + l;
        float dlt = delta[idx*DI + d];
        float uu  = ucv  [idx*DI + d];
        float Bv  = dbl[idx*96 + DTR + n];
        float Cv  = dbl[idx*96 + DTR + NN + n];
        float du  = dlt * uu;
        h = fmaf(__expf(dlt * A), h, du * Bv);
        float p = h * Cv;
        p += __shfl_xor_sync(0xffffffffu, p, 8);
        p += __shfl_xor_sync(0xffffffffu, p, 4);
        p += __shfl_xor_sync(0xffffffffu, p, 2);
        p += __shfl_xor_sync(0xffffffffu, p, 1);
        if (n == 0) {
            float r  = ur[idx*(2*DI) + DI + d];
            float sr = r / (1.f + __expf(-r));
            yg[idx*DI + d] = (p + uu * Dd) * sr;
        }
    }
}

// ---------------------------------------------------------------------------
// Launch
// ---------------------------------------------------------------------------
extern "C" void kernel_launch(void* const* d_in, const int* in_sizes, int n_in,
                              void* d_out, int out_size)
{
    const int*   x     = (const int*)  d_in[0];
    const int*   qid   = (const int*)  d_in[1];
    const float* emb   = (const float*)d_in[2];
    const float* qc    = (const float*)d_in[3];
    const float* ln0g  = (const float*)d_in[4];
    const float* ln0b  = (const float*)d_in[5];
    const float* inw   = (const float*)d_in[6];   // (4096,1024)
    const float* convw = (const float*)d_in[7];   // (2048,4)
    const float* convb = (const float*)d_in[8];
    const float* xpw   = (const float*)d_in[9];   // (96,2048)
    const float* dtw   = (const float*)d_in[10];  // (2048,64)
    const float* dtb   = (const float*)d_in[11];
    const float* alog  = (const float*)d_in[12];  // (2048,16)
    const float* dpar  = (const float*)d_in[13];
    const float* outw  = (const float*)d_in[14];  // (1024,2048)
    const float* ln1g  = (const float*)d_in[15];
    const float* ln1b  = (const float*)d_in[16];
    const float* fcw   = (const float*)d_in[17];  // (4000,1024)
    const float* fcb   = (const float*)d_in[18];
    float* out = (float*)d_out;

    float *item, *ur, *ucv, *dbl, *delta, *yg, *hout, *lnout;
    cudaGetSymbolAddress((void**)&item,  g_item);
    cudaGetSymbolAddress((void**)&ur,    g_ur);
    cudaGetSymbolAddress((void**)&ucv,   g_ucv);
    cudaGetSymbolAddress((void**)&dbl,   g_dbl);
    cudaGetSymbolAddress((void**)&delta, g_delta);
    cudaGetSymbolAddress((void**)&yg,    g_yg);
    cudaGetSymbolAddress((void**)&hout,  g_hout);
    cudaGetSymbolAddress((void**)&lnout, g_lnout);

    // 1) embed + concat + LN0
    embed_ln0_kernel<<<BL, 256>>>(x, qid, emb, qc, ln0g, ln0b, item);

    // 2) in_proj: (8192,1024) @ (4096,1024)^T -> (8192,4096)
    gemm_tn<0><<<dim3(2*DI/128, BL/128), 256>>>(item, DM, inw, DM, ur, 2*DI,
                                                BL, 2*DI, DM, nullptr);

    // 3) depthwise conv + SiLU -> ucv (8192,2048)
    conv_silu_kernel<<<dim3(DI/256, BB), 256>>>(ur, convw, convb, ucv);

    // 4) x_proj: (8192,2048) @ (96,2048)^T -> dbl (8192,96)
    gemm_tn<0><<<dim3(1, BL/128), 256>>>(ucv, DI, xpw, DI, dbl, 96,
                                         BL, 96, DI, nullptr);

    // 5) dt_proj + softplus: dbl[:, :64] @ (2048,64)^T + b -> delta (8192,2048)
    gemm_tn<1><<<dim3(DI/128, BL/128), 256>>>(dbl, 96, dtw, DTR, delta, DI,
                                              BL, DI, DTR, dtb);

    // 6) selective scan + gate -> yg (8192,2048)
    scan_kernel<<<dim3(DI/16, BB), 256>>>(delta, ucv, dbl, ur, alog, dpar, yg);

    // 7) out_proj: (8192,2048) @ (1024,2048)^T -> hout (8192,1024)
    gemm_tn<0><<<dim3(DM/128, BL/128), 256>>>(yg, DI, outw, DI, hout, DM,
                                              BL, DM, DI, nullptr);

    // 8) residual + LN1 -> lnout
    add_ln_kernel<<<BL, 256>>>(hout, item, ln1g, ln1b, lnout);

    // 9) fc + bias + sigmoid -> out (8192,4000)
    gemm_tn<2><<<dim3((QUES+127)/128, BL/128), 256>>>(lnout, DM, fcw, DM, out, QUES,
                                                      BL, QUES, DM, fcb);
}

// round 3
// speedup vs baseline: 2.1240x; 2.1240x over previous
#include <cuda_runtime.h>
#include <cuda_bf16.h>
#include <cstdint>
#include <math.h>

// ---------------------------------------------------------------------------
// Problem constants
// ---------------------------------------------------------------------------
#define BB   8
#define LL   1024
#define BL   (BB*LL)          // 8192 tokens
#define QUES 4000
#define EMB  256
#define DM   1024
#define DI   2048
#define NN   16
#define DTR  64
#define KK   4

// ---------------------------------------------------------------------------
// Scratch (static device allocations; no cudaMalloc allowed)
// ---------------------------------------------------------------------------
__device__ float g_item [BL*DM];
__device__ float g_ur   [(size_t)BL*2*DI];
__device__ float g_ucv  [(size_t)BL*DI];
__device__ float g_dbl  [BL*96];
__device__ float g_delta[(size_t)BL*DI];
__device__ float g_yg   [(size_t)BL*DI];
__device__ float g_hout [BL*DM];
__device__ float g_lnout[BL*DM];

// ---------------------------------------------------------------------------
// cp.async helpers (sm_80+, arch-generic)
// ---------------------------------------------------------------------------
__device__ __forceinline__ uint32_t smem_u32(const void* p) {
    uint32_t a;
    asm("{ .reg .u64 t; cvta.to.shared.u64 t, %1; cvt.u32.u64 %0, t; }" : "=r"(a) : "l"(p));
    return a;
}
__device__ __forceinline__ void cp_async16(uint32_t dst, const void* src, int src_bytes) {
    asm volatile("cp.async.cg.shared.global [%0], [%1], 16, %2;"
                 :: "r"(dst), "l"(src), "r"(src_bytes) : "memory");
}
#define CP_COMMIT()  asm volatile("cp.async.commit_group;" ::: "memory")
#define CP_WAIT(n)   asm volatile("cp.async.wait_group %0;" :: "n"(n) : "memory")

__device__ __forceinline__ uint32_t f2tf32(float f) {
    uint32_t r;
    asm("cvt.rna.tf32.f32 %0, %1;" : "=r"(r) : "f"(f));
    return r;
}
__device__ __forceinline__ void mma_tf32(float& c0, float& c1, float& c2, float& c3,
                                         uint32_t a0, uint32_t a1, uint32_t a2, uint32_t a3,
                                         uint32_t b0, uint32_t b1) {
    asm volatile(
        "mma.sync.aligned.m16n8k8.row.col.f32.tf32.tf32.f32 "
        "{%0,%1,%2,%3}, {%4,%5,%6,%7}, {%8,%9}, {%0,%1,%2,%3};"
        : "+f"(c0), "+f"(c1), "+f"(c2), "+f"(c3)
        : "r"(a0), "r"(a1), "r"(a2), "r"(a3), "r"(b0), "r"(b1));
}

// ---------------------------------------------------------------------------
// TF32 tensor-core GEMM:  C[M,N] = A[M,K](lda) * B[N,K](ldb)^T
// CTA tile 128x128, BK=32, 256 threads (8 warps, each 64x32 warp tile),
// double-buffered cp.async pipeline.
// EPI: 0 = none, 1 = bias+softplus, 2 = bias+sigmoid
// Requirements: M % 128 == 0, K % 32 == 0, 16B-aligned rows. N arbitrary.
// ---------------------------------------------------------------------------
#define PAD 36                     // 32 floats + 4 pad (keeps 16B alignment, no LDS conflicts)
#define TILE_F (128 * PAD)         // floats per (A or B) tile buffer

template<int EPI>
__global__ __launch_bounds__(256)
void gemm_mma(const float* __restrict__ A, int lda,
              const float* __restrict__ B, int ldb,
              float* __restrict__ C, int ldc,
              int M, int N, int K, const float* __restrict__ bias)
{
    extern __shared__ float sm[];   // [2 bufs][A tile | B tile]
    const int tid  = threadIdx.x;
    const int lane = tid & 31;
    const int wid  = tid >> 5;
    const int g    = lane >> 2;     // 0..7
    const int tg   = lane & 3;      // 0..3

    const int m0 = blockIdx.y * 128;
    const int n0 = blockIdx.x * 128;
    const int warp_m = (wid >> 2) * 64;   // 0 or 64
    const int warp_n = (wid & 3) * 32;    // 0,32,64,96

    const uint32_t smem_base = smem_u32(sm);

    float acc[4][4][4];
    #pragma unroll
    for (int mi = 0; mi < 4; mi++)
        #pragma unroll
        for (int ni = 0; ni < 4; ni++)
            #pragma unroll
            for (int r = 0; r < 4; r++) acc[mi][ni][r] = 0.f;

    const int NC = K >> 5;

    // chunk loader: A rows always valid (M%128==0); B rows guarded via src-size 0
    auto load_chunk = [&](int ch, int buf) {
        const int k0 = ch << 5;
        float* bufp = sm + buf * (2 * TILE_F);
        uint32_t aBase = smem_base + (uint32_t)(buf * 2 * TILE_F) * 4u;
        uint32_t bBase = aBase + (uint32_t)TILE_F * 4u;
        #pragma unroll
        for (int it = 0; it < 4; it++) {
            int idx = tid + it * 256;
            int row = idx >> 3, gq = idx & 7;
            cp_async16(aBase + (uint32_t)(row * PAD + gq * 4) * 4u,
                       A + (size_t)(m0 + row) * lda + k0 + gq * 4, 16);
        }
        #pragma unroll
        for (int it = 0; it < 4; it++) {
            int idx = tid + it * 256;
            int row = idx >> 3, gq = idx & 7;
            int gn = n0 + row;
            int ok = (gn < N) ? 16 : 0;
            const float* src = B + (size_t)(ok ? gn : 0) * ldb + k0 + gq * 4;
            cp_async16(bBase + (uint32_t)(row * PAD + gq * 4) * 4u, src, ok);
        }
        (void)bufp;
    };

    load_chunk(0, 0);
    CP_COMMIT();

    for (int ch = 0; ch < NC; ch++) {
        if (ch + 1 < NC) { load_chunk(ch + 1, (ch + 1) & 1); CP_COMMIT(); CP_WAIT(1); }
        else             { CP_WAIT(0); }
        __syncthreads();

        const float* As = sm + (ch & 1) * (2 * TILE_F);
        const float* Bs = As + TILE_F;

        #pragma unroll
        for (int ks = 0; ks < 4; ks++) {
            const int kc = ks * 8;
            uint32_t af[4][4], bf[4][2];
            #pragma unroll
            for (int mi = 0; mi < 4; mi++) {
                int r0 = warp_m + mi * 16 + g;
                af[mi][0] = f2tf32(As[(r0    ) * PAD + kc + tg    ]);
                af[mi][1] = f2tf32(As[(r0 + 8) * PAD + kc + tg    ]);
                af[mi][2] = f2tf32(As[(r0    ) * PAD + kc + tg + 4]);
                af[mi][3] = f2tf32(As[(r0 + 8) * PAD + kc + tg + 4]);
            }
            #pragma unroll
            for (int ni = 0; ni < 4; ni++) {
                int c0 = warp_n + ni * 8 + g;
                bf[ni][0] = f2tf32(Bs[c0 * PAD + kc + tg    ]);
                bf[ni][1] = f2tf32(Bs[c0 * PAD + kc + tg + 4]);
            }
            #pragma unroll
            for (int mi = 0; mi < 4; mi++)
                #pragma unroll
                for (int ni = 0; ni < 4; ni++)
                    mma_tf32(acc[mi][ni][0], acc[mi][ni][1], acc[mi][ni][2], acc[mi][ni][3],
                             af[mi][0], af[mi][1], af[mi][2], af[mi][3],
                             bf[ni][0], bf[ni][1]);
        }
        __syncthreads();
    }

    // Epilogue: c0,c1 -> (row, col..col+1); c2,c3 -> (row+8, col..col+1)
    #pragma unroll
    for (int mi = 0; mi < 4; mi++) {
        #pragma unroll
        for (int ni = 0; ni < 4; ni++) {
            int row = m0 + warp_m + mi * 16 + g;
            int col = n0 + warp_n + ni * 8 + 2 * tg;
            float v[4] = {acc[mi][ni][0], acc[mi][ni][1], acc[mi][ni][2], acc[mi][ni][3]};
            if (EPI != 0) {
                #pragma unroll
                for (int j = 0; j < 4; j++) {
                    int cc = col + (j & 1);
                    if (cc < N) {
                        float t = v[j] + bias[cc];
                        if (EPI == 1) v[j] = (t > 20.f) ? t : log1pf(expf(t));
                        else          v[j] = 1.f / (1.f + expf(-t));
                    }
                }
            }
            if (col + 1 < N) {
                *(float2*)(C + (size_t)row * ldc + col)       = make_float2(v[0], v[1]);
                *(float2*)(C + (size_t)(row + 8) * ldc + col) = make_float2(v[2], v[3]);
            } else if (col < N) {
                C[(size_t)row * ldc + col]       = v[0];
                C[(size_t)(row + 8) * ldc + col] = v[2];
            }
        }
    }
}

// ---------------------------------------------------------------------------
// Embedding gather + concat + LayerNorm0
// ---------------------------------------------------------------------------
__global__ void embed_ln0_kernel(const int* __restrict__ x, const int* __restrict__ qid,
                                 const float* __restrict__ emb, const float* __restrict__ qc,
                                 const float* __restrict__ g, const float* __restrict__ b,
                                 float* __restrict__ item)
{
    int tok = blockIdx.x;
    int t   = threadIdx.x;
    int xv  = x[tok];
    int qv  = qid[tok];

    float v[4];
    v[0] = emb[(size_t)xv*EMB + t];
    v[1] = qc [(size_t)qv*768 + t];
    v[2] = qc [(size_t)qv*768 + 256 + t];
    v[3] = qc [(size_t)qv*768 + 512 + t];

    float s  = v[0]+v[1]+v[2]+v[3];
    float sq = v[0]*v[0]+v[1]*v[1]+v[2]*v[2]+v[3]*v[3];
    #pragma unroll
    for (int o = 16; o > 0; o >>= 1) {
        s  += __shfl_xor_sync(0xffffffffu, s,  o);
        sq += __shfl_xor_sync(0xffffffffu, sq, o);
    }
    __shared__ float ws[8], wq[8];
    int lane = t & 31, warp = t >> 5;
    if (lane == 0) { ws[warp] = s; wq[warp] = sq; }
    __syncthreads();
    __shared__ float s_mean, s_rstd;
    if (t == 0) {
        float ts = 0.f, tq = 0.f;
        #pragma unroll
        for (int i = 0; i < 8; i++) { ts += ws[i]; tq += wq[i]; }
        float mean = ts * (1.0f/DM);
        float var  = tq * (1.0f/DM) - mean*mean;
        s_mean = mean;
        s_rstd = rsqrtf(var + 1e-12f);
    }
    __syncthreads();
    float mean = s_mean, rstd = s_rstd;
    #pragma unroll
    for (int i = 0; i < 4; i++) {
        int j = t + i*256;
        item[(size_t)tok*DM + j] = (v[i] - mean) * rstd * g[j] + b[j];
    }
}

// ---------------------------------------------------------------------------
// Residual add + LayerNorm1
// ---------------------------------------------------------------------------
__global__ void add_ln_kernel(const float* __restrict__ a, const float* __restrict__ res,
                              const float* __restrict__ g, const float* __restrict__ b,
                              float* __restrict__ out)
{
    int tok = blockIdx.x;
    int t   = threadIdx.x;
    float v[4];
    #pragma unroll
    for (int i = 0; i < 4; i++) {
        int j = t + i*256;
        v[i] = a[(size_t)tok*DM + j] + res[(size_t)tok*DM + j];
    }
    float s  = v[0]+v[1]+v[2]+v[3];
    float sq = v[0]*v[0]+v[1]*v[1]+v[2]*v[2]+v[3]*v[3];
    #pragma unroll
    for (int o = 16; o > 0; o >>= 1) {
        s  += __shfl_xor_sync(0xffffffffu, s,  o);
        sq += __shfl_xor_sync(0xffffffffu, sq, o);
    }
    __shared__ float ws[8], wq[8];
    int lane = t & 31, warp = t >> 5;
    if (lane == 0) { ws[warp] = s; wq[warp] = sq; }
    __syncthreads();
    __shared__ float s_mean, s_rstd;
    if (t == 0) {
        float ts = 0.f, tq = 0.f;
        #pragma unroll
        for (int i = 0; i < 8; i++) { ts += ws[i]; tq += wq[i]; }
        float mean = ts * (1.0f/DM);
        float var  = tq * (1.0f/DM) - mean*mean;
        s_mean = mean;
        s_rstd = rsqrtf(var + 1e-12f);
    }
    __syncthreads();
    float mean = s_mean, rstd = s_rstd;
    #pragma unroll
    for (int i = 0; i < 4; i++) {
        int j = t + i*256;
        out[(size_t)tok*DM + j] = (v[i] - mean) * rstd * g[j] + b[j];
    }
}

// ---------------------------------------------------------------------------
// Depthwise causal conv (K=4) + SiLU
// ---------------------------------------------------------------------------
__global__ void conv_silu_kernel(const float* __restrict__ ur,
                                 const float* __restrict__ w,
                                 const float* __restrict__ cb,
                                 float* __restrict__ out)
{
    int d = blockIdx.x * 256 + threadIdx.x;
    int b = blockIdx.y;
    float w0 = w[d*4+0], w1 = w[d*4+1], w2 = w[d*4+2], w3 = w[d*4+3];
    float bias = cb[d];
    float x0 = 0.f, x1 = 0.f, x2 = 0.f;
    size_t rbase = (size_t)b * LL;
    for (int l = 0; l < LL; l++) {
        size_t idx = rbase + l;
        float xc = ur[idx*(2*DI) + d];
        float c  = fmaf(x0, w0, fmaf(x1, w1, fmaf(x2, w2, fmaf(xc, w3, bias))));
        out[idx*DI + d] = c / (1.f + __expf(-c));
        x0 = x1; x1 = x2; x2 = xc;
    }
}

// ---------------------------------------------------------------------------
// Selective scan + gate
// ---------------------------------------------------------------------------
__global__ void scan_kernel(const float* __restrict__ delta,
                            const float* __restrict__ ucv,
                            const float* __restrict__ dbl,
                            const float* __restrict__ ur,
                            const float* __restrict__ A_log,
                            const float* __restrict__ D_param,
                            float* __restrict__ yg)
{
    int t = threadIdx.x;
    int n = t & 15;
    int d = blockIdx.x * 16 + (t >> 4);
    int b = blockIdx.y;

    float A  = -expf(A_log[d*NN + n]);
    float Dd = D_param[d];
    float h  = 0.f;
    size_t base = (size_t)b * LL;

    for (int l = 0; l < LL; l++) {
        size_t idx = base + l;
        float dlt = delta[idx*DI + d];
        float uu  = ucv  [idx*DI + d];
        float Bv  = dbl[idx*96 + DTR + n];
        float Cv  = dbl[idx*96 + DTR + NN + n];
        float du  = dlt * uu;
        h = fmaf(__expf(dlt * A), h, du * Bv);
        float p = h * Cv;
        p += __shfl_xor_sync(0xffffffffu, p, 8);
        p += __shfl_xor_sync(0xffffffffu, p, 4);
        p += __shfl_xor_sync(0xffffffffu, p, 2);
        p += __shfl_xor_sync(0xffffffffu, p, 1);
        if (n == 0) {
            float r  = ur[idx*(2*DI) + DI + d];
            float sr = r / (1.f + __expf(-r));
            yg[idx*DI + d] = (p + uu * Dd) * sr;
        }
    }
}

// ---------------------------------------------------------------------------
// Launch
// ---------------------------------------------------------------------------
extern "C" void kernel_launch(void* const* d_in, const int* in_sizes, int n_in,
                              void* d_out, int out_size)
{
    const int*   x     = (const int*)  d_in[0];
    const int*   qid   = (const int*)  d_in[1];
    const float* emb   = (const float*)d_in[2];
    const float* qc    = (const float*)d_in[3];
    const float* ln0g  = (const float*)d_in[4];
    const float* ln0b  = (const float*)d_in[5];
    const float* inw   = (const float*)d_in[6];   // (4096,1024)
    const float* convw = (const float*)d_in[7];   // (2048,4)
    const float* convb = (const float*)d_in[8];
    const float* xpw   = (const float*)d_in[9];   // (96,2048)
    const float* dtw   = (const float*)d_in[10];  // (2048,64)
    const float* dtb   = (const float*)d_in[11];
    const float* alog  = (const float*)d_in[12];  // (2048,16)
    const float* dpar  = (const float*)d_in[13];
    const float* outw  = (const float*)d_in[14];  // (1024,2048)
    const float* ln1g  = (const float*)d_in[15];
    const float* ln1b  = (const float*)d_in[16];
    const float* fcw   = (const float*)d_in[17];  // (4000,1024)
    const float* fcb   = (const float*)d_in[18];
    float* out = (float*)d_out;

    float *item, *ur, *ucv, *dbl, *delta, *yg, *hout, *lnout;
    cudaGetSymbolAddress((void**)&item,  g_item);
    cudaGetSymbolAddress((void**)&ur,    g_ur);
    cudaGetSymbolAddress((void**)&ucv,   g_ucv);
    cudaGetSymbolAddress((void**)&dbl,   g_dbl);
    cudaGetSymbolAddress((void**)&delta, g_delta);
    cudaGetSymbolAddress((void**)&yg,    g_yg);
    cudaGetSymbolAddress((void**)&hout,  g_hout);
    cudaGetSymbolAddress((void**)&lnout, g_lnout);

    const int SMEM = 2 * 2 * TILE_F * 4;   // 73,728 B
    cudaFuncSetAttribute(gemm_mma<0>, cudaFuncAttributeMaxDynamicSharedMemorySize, SMEM);
    cudaFuncSetAttribute(gemm_mma<1>, cudaFuncAttributeMaxDynamicSharedMemorySize, SMEM);
    cudaFuncSetAttribute(gemm_mma<2>, cudaFuncAttributeMaxDynamicSharedMemorySize, SMEM);

    // 1) embed + concat + LN0
    embed_ln0_kernel<<<BL, 256>>>(x, qid, emb, qc, ln0g, ln0b, item);

    // 2) in_proj: (8192,1024) @ (4096,1024)^T -> ur (8192,4096)
    gemm_mma<0><<<dim3(2*DI/128, BL/128), 256, SMEM>>>(item, DM, inw, DM, ur, 2*DI,
                                                       BL, 2*DI, DM, nullptr);

    // 3) depthwise conv + SiLU -> ucv (8192,2048)
    conv_silu_kernel<<<dim3(DI/256, BB), 256>>>(ur, convw, convb, ucv);

    // 4) x_proj: (8192,2048) @ (96,2048)^T -> dbl (8192,96)
    gemm_mma<0><<<dim3(1, BL/128), 256, SMEM>>>(ucv, DI, xpw, DI, dbl, 96,
                                                BL, 96, DI, nullptr);

    // 5) dt_proj + softplus: dbl[:, :64] @ (2048,64)^T + b -> delta (8192,2048)
    gemm_mma<1><<<dim3(DI/128, BL/128), 256, SMEM>>>(dbl, 96, dtw, DTR, delta, DI,
                                                     BL, DI, DTR, dtb);

    // 6) selective scan + gate -> yg (8192,2048)
    scan_kernel<<<dim3(DI/16, BB), 256>>>(delta, ucv, dbl, ur, alog, dpar, yg);

    // 7) out_proj: (8192,2048) @ (1024,2048)^T -> hout (8192,1024)
    gemm_mma<0><<<dim3(DM/128, BL/128), 256, SMEM>>>(yg, DI, outw, DI, hout, DM,
                                                     BL, DM, DI, nullptr);

    // 8) residual + LN1 -> lnout
    add_ln_kernel<<<BL, 256>>>(hout, item, ln1g, ln1b, lnout);

    // 9) fc + bias + sigmoid -> out (8192,4000)
    gemm_mma<2><<<dim3((QUES+127)/128, BL/128), 256, SMEM>>>(lnout, DM, fcw, DM, out, QUES,
                                                             BL, QUES, DM, fcb);
}

// round 4
// speedup vs baseline: 2.6157x; 1.2315x over previous
#include <cuda_runtime.h>
#include <cuda_bf16.h>
#include <cstdint>
#include <math.h>

// ---------------------------------------------------------------------------
// Problem constants
// ---------------------------------------------------------------------------
#define BB   8
#define LL   1024
#define BL   (BB*LL)          // 8192 tokens
#define QUES 4000
#define EMB  256
#define DM   1024
#define DI   2048
#define NN   16
#define DTR  64
#define KK   4

// ---------------------------------------------------------------------------
// Scratch (static device allocations; no cudaMalloc allowed)
// ---------------------------------------------------------------------------
__device__ float g_item [BL*DM];
__device__ float g_ur   [(size_t)BL*2*DI];
__device__ float g_ucv  [(size_t)BL*DI];
__device__ float g_dbl  [BL*96];
__device__ float g_delta[(size_t)BL*DI];
__device__ float g_yg   [(size_t)BL*DI];
__device__ float g_hout [BL*DM];
__device__ float g_lnout[BL*DM];

// ---------------------------------------------------------------------------
// cp.async + mma helpers (arch-generic PTX, sm_80+)
// ---------------------------------------------------------------------------
__device__ __forceinline__ uint32_t smem_u32(const void* p) {
    uint32_t a;
    asm("{ .reg .u64 t; cvta.to.shared.u64 t, %1; cvt.u32.u64 %0, t; }" : "=r"(a) : "l"(p));
    return a;
}
__device__ __forceinline__ void cp_async16(uint32_t dst, const void* src, int src_bytes) {
    asm volatile("cp.async.cg.shared.global [%0], [%1], 16, %2;"
                 :: "r"(dst), "l"(src), "r"(src_bytes) : "memory");
}
#define CP_COMMIT()  asm volatile("cp.async.commit_group;" ::: "memory")
#define CP_WAIT(n)   asm volatile("cp.async.wait_group %0;" :: "n"(n) : "memory")

__device__ __forceinline__ void mma_tf32(float& c0, float& c1, float& c2, float& c3,
                                         uint32_t a0, uint32_t a1, uint32_t a2, uint32_t a3,
                                         uint32_t b0, uint32_t b1) {
    asm volatile(
        "mma.sync.aligned.m16n8k8.row.col.f32.tf32.tf32.f32 "
        "{%0,%1,%2,%3}, {%4,%5,%6,%7}, {%8,%9}, {%0,%1,%2,%3};"
        : "+f"(c0), "+f"(c1), "+f"(c2), "+f"(c3)
        : "r"(a0), "r"(a1), "r"(a2), "r"(a3), "r"(b0), "r"(b1));
}

// ---------------------------------------------------------------------------
// TF32 tensor-core GEMM:  C[M,N] = A[M,K](lda) * B[N,K](ldb)^T
// CTA tile 128x128, BK=32, 256 threads (8 warps, 64x32 warp tiles),
// double-buffered cp.async, raw-fp32-as-tf32 operands (no cvt).
// EPI: 0 = none, 1 = bias+softplus, 2 = bias+sigmoid
// ---------------------------------------------------------------------------
#define PAD 36
#define TILE_F (128 * PAD)

template<int EPI>
__global__ __launch_bounds__(256, 2)
void gemm_mma(const float* __restrict__ A, int lda,
              const float* __restrict__ B, int ldb,
              float* __restrict__ C, int ldc,
              int M, int N, int K, const float* __restrict__ bias)
{
    extern __shared__ float smf[];
    const uint32_t* smu = (const uint32_t*)smf;
    const int tid  = threadIdx.x;
    const int lane = tid & 31;
    const int wid  = tid >> 5;
    const int g    = lane >> 2;
    const int tg   = lane & 3;

    const int m0 = blockIdx.y * 128;
    const int n0 = blockIdx.x * 128;
    const int warp_m = (wid >> 2) * 64;
    const int warp_n = (wid & 3) * 32;

    const uint32_t smem_base = smem_u32(smf);

    float acc[4][4][4];
    #pragma unroll
    for (int mi = 0; mi < 4; mi++)
        #pragma unroll
        for (int ni = 0; ni < 4; ni++)
            #pragma unroll
            for (int r = 0; r < 4; r++) acc[mi][ni][r] = 0.f;

    const int NC = K >> 5;

    auto load_chunk = [&](int ch, int buf) {
        const int k0 = ch << 5;
        uint32_t aBase = smem_base + (uint32_t)(buf * 2 * TILE_F) * 4u;
        uint32_t bBase = aBase + (uint32_t)TILE_F * 4u;
        #pragma unroll
        for (int it = 0; it < 4; it++) {
            int idx = tid + it * 256;
            int row = idx >> 3, gq = idx & 7;
            cp_async16(aBase + (uint32_t)(row * PAD + gq * 4) * 4u,
                       A + (size_t)(m0 + row) * lda + k0 + gq * 4, 16);
        }
        #pragma unroll
        for (int it = 0; it < 4; it++) {
            int idx = tid + it * 256;
            int row = idx >> 3, gq = idx & 7;
            int gn = n0 + row;
            int ok = (gn < N) ? 16 : 0;
            const float* src = B + (size_t)(ok ? gn : 0) * ldb + k0 + gq * 4;
            cp_async16(bBase + (uint32_t)(row * PAD + gq * 4) * 4u, src, ok);
        }
    };

    load_chunk(0, 0);
    CP_COMMIT();

    for (int ch = 0; ch < NC; ch++) {
        if (ch + 1 < NC) { load_chunk(ch + 1, (ch + 1) & 1); CP_COMMIT(); CP_WAIT(1); }
        else             { CP_WAIT(0); }
        __syncthreads();

        const uint32_t* As = smu + (ch & 1) * (2 * TILE_F);
        const uint32_t* Bs = As + TILE_F;

        #pragma unroll
        for (int ks = 0; ks < 4; ks++) {
            const int kc = ks * 8;
            uint32_t af[4][4], bf[4][2];
            #pragma unroll
            for (int mi = 0; mi < 4; mi++) {
                int r0 = warp_m + mi * 16 + g;
                af[mi][0] = As[(r0    ) * PAD + kc + tg    ];
                af[mi][1] = As[(r0 + 8) * PAD + kc + tg    ];
                af[mi][2] = As[(r0    ) * PAD + kc + tg + 4];
                af[mi][3] = As[(r0 + 8) * PAD + kc + tg + 4];
            }
            #pragma unroll
            for (int ni = 0; ni < 4; ni++) {
                int c0 = warp_n + ni * 8 + g;
                bf[ni][0] = Bs[c0 * PAD + kc + tg    ];
                bf[ni][1] = Bs[c0 * PAD + kc + tg + 4];
            }
            #pragma unroll
            for (int mi = 0; mi < 4; mi++)
                #pragma unroll
                for (int ni = 0; ni < 4; ni++)
                    mma_tf32(acc[mi][ni][0], acc[mi][ni][1], acc[mi][ni][2], acc[mi][ni][3],
                             af[mi][0], af[mi][1], af[mi][2], af[mi][3],
                             bf[ni][0], bf[ni][1]);
        }
        __syncthreads();
    }

    #pragma unroll
    for (int mi = 0; mi < 4; mi++) {
        #pragma unroll
        for (int ni = 0; ni < 4; ni++) {
            int row = m0 + warp_m + mi * 16 + g;
            int col = n0 + warp_n + ni * 8 + 2 * tg;
            float v[4] = {acc[mi][ni][0], acc[mi][ni][1], acc[mi][ni][2], acc[mi][ni][3]};
            if (EPI != 0) {
                #pragma unroll
                for (int j = 0; j < 4; j++) {
                    int cc = col + (j & 1);
                    if (cc < N) {
                        float t = v[j] + bias[cc];
                        if (EPI == 1) v[j] = (t > 20.f) ? t : log1pf(expf(t));
                        else          v[j] = 1.f / (1.f + expf(-t));
                    }
                }
            }
            if (col + 1 < N) {
                *(float2*)(C + (size_t)row * ldc + col)       = make_float2(v[0], v[1]);
                *(float2*)(C + (size_t)(row + 8) * ldc + col) = make_float2(v[2], v[3]);
            } else if (col < N) {
                C[(size_t)row * ldc + col]       = v[0];
                C[(size_t)(row + 8) * ldc + col] = v[2];
            }
        }
    }
}

// ---------------------------------------------------------------------------
// Embedding gather + concat + LayerNorm0
// ---------------------------------------------------------------------------
__global__ void embed_ln0_kernel(const int* __restrict__ x, const int* __restrict__ qid,
                                 const float* __restrict__ emb, const float* __restrict__ qc,
                                 const float* __restrict__ g, const float* __restrict__ b,
                                 float* __restrict__ item)
{
    int tok = blockIdx.x;
    int t   = threadIdx.x;
    int xv  = x[tok];
    int qv  = qid[tok];

    float v[4];
    v[0] = emb[(size_t)xv*EMB + t];
    v[1] = qc [(size_t)qv*768 + t];
    v[2] = qc [(size_t)qv*768 + 256 + t];
    v[3] = qc [(size_t)qv*768 + 512 + t];

    float s  = v[0]+v[1]+v[2]+v[3];
    float sq = v[0]*v[0]+v[1]*v[1]+v[2]*v[2]+v[3]*v[3];
    #pragma unroll
    for (int o = 16; o > 0; o >>= 1) {
        s  += __shfl_xor_sync(0xffffffffu, s,  o);
        sq += __shfl_xor_sync(0xffffffffu, sq, o);
    }
    __shared__ float ws[8], wq[8];
    int lane = t & 31, warp = t >> 5;
    if (lane == 0) { ws[warp] = s; wq[warp] = sq; }
    __syncthreads();
    __shared__ float s_mean, s_rstd;
    if (t == 0) {
        float ts = 0.f, tq = 0.f;
        #pragma unroll
        for (int i = 0; i < 8; i++) { ts += ws[i]; tq += wq[i]; }
        float mean = ts * (1.0f/DM);
        float var  = tq * (1.0f/DM) - mean*mean;
        s_mean = mean;
        s_rstd = rsqrtf(var + 1e-12f);
    }
    __syncthreads();
    float mean = s_mean, rstd = s_rstd;
    #pragma unroll
    for (int i = 0; i < 4; i++) {
        int j = t + i*256;
        item[(size_t)tok*DM + j] = (v[i] - mean) * rstd * g[j] + b[j];
    }
}

// ---------------------------------------------------------------------------
// Residual add + LayerNorm1
// ---------------------------------------------------------------------------
__global__ void add_ln_kernel(const float* __restrict__ a, const float* __restrict__ res,
                              const float* __restrict__ g, const float* __restrict__ b,
                              float* __restrict__ out)
{
    int tok = blockIdx.x;
    int t   = threadIdx.x;
    float v[4];
    #pragma unroll
    for (int i = 0; i < 4; i++) {
        int j = t + i*256;
        v[i] = a[(size_t)tok*DM + j] + res[(size_t)tok*DM + j];
    }
    float s  = v[0]+v[1]+v[2]+v[3];
    float sq = v[0]*v[0]+v[1]*v[1]+v[2]*v[2]+v[3]*v[3];
    #pragma unroll
    for (int o = 16; o > 0; o >>= 1) {
        s  += __shfl_xor_sync(0xffffffffu, s,  o);
        sq += __shfl_xor_sync(0xffffffffu, sq, o);
    }
    __shared__ float ws[8], wq[8];
    int lane = t & 31, warp = t >> 5;
    if (lane == 0) { ws[warp] = s; wq[warp] = sq; }
    __syncthreads();
    __shared__ float s_mean, s_rstd;
    if (t == 0) {
        float ts = 0.f, tq = 0.f;
        #pragma unroll
        for (int i = 0; i < 8; i++) { ts += ws[i]; tq += wq[i]; }
        float mean = ts * (1.0f/DM);
        float var  = tq * (1.0f/DM) - mean*mean;
        s_mean = mean;
        s_rstd = rsqrtf(var + 1e-12f);
    }
    __syncthreads();
    float mean = s_mean, rstd = s_rstd;
    #pragma unroll
    for (int i = 0; i < 4; i++) {
        int j = t + i*256;
        out[(size_t)tok*DM + j] = (v[i] - mean) * rstd * g[j] + b[j];
    }
}

// ---------------------------------------------------------------------------
// Depthwise causal conv (K=4) + SiLU — chunked over l for occupancy.
// grid (DI/256, LL/CHUNK, BB); each thread: one d, CHUNK l-steps.
// ---------------------------------------------------------------------------
#define CONV_CHUNK 64
__global__ void conv_silu_kernel(const float* __restrict__ ur,
                                 const float* __restrict__ w,
                                 const float* __restrict__ cb,
                                 float* __restrict__ out)
{
    int d  = blockIdx.x * 256 + threadIdx.x;
    int l0 = blockIdx.y * CONV_CHUNK;
    int b  = blockIdx.z;
    float w0 = w[d*4+0], w1 = w[d*4+1], w2 = w[d*4+2], w3 = w[d*4+3];
    float bias = cb[d];
    size_t rbase = (size_t)b * LL;

    float x0 = 0.f, x1 = 0.f, x2 = 0.f;
    if (l0 >= 3) {
        x0 = ur[(rbase + l0 - 3)*(2*DI) + d];
        x1 = ur[(rbase + l0 - 2)*(2*DI) + d];
        x2 = ur[(rbase + l0 - 1)*(2*DI) + d];
    } else {
        if (l0 >= 1) x2 = ur[(rbase + l0 - 1)*(2*DI) + d];
        if (l0 >= 2) x1 = ur[(rbase + l0 - 2)*(2*DI) + d];
    }
    #pragma unroll 4
    for (int l = l0; l < l0 + CONV_CHUNK; l++) {
        size_t idx = rbase + l;
        float xc = ur[idx*(2*DI) + d];
        float c  = fmaf(x0, w0, fmaf(x1, w1, fmaf(x2, w2, fmaf(xc, w3, bias))));
        out[idx*DI + d] = c / (1.f + __expf(-c));
        x0 = x1; x1 = x2; x2 = xc;
    }
}

// ---------------------------------------------------------------------------
// Selective scan + gate
// ---------------------------------------------------------------------------
__global__ void scan_kernel(const float* __restrict__ delta,
                            const float* __restrict__ ucv,
                            const float* __restrict__ dbl,
                            const float* __restrict__ ur,
                            const float* __restrict__ A_log,
                            const float* __restrict__ D_param,
                            float* __restrict__ yg)
{
    int t = threadIdx.x;
    int n = t & 15;
    int d = blockIdx.x * 16 + (t >> 4);
    int b = blockIdx.y;

    float A  = -expf(A_log[d*NN + n]);
    float Dd = D_param[d];
    float h  = 0.f;
    size_t base = (size_t)b * LL;

    for (int l = 0; l < LL; l++) {
        size_t idx = base + l;
        float dlt = delta[idx*DI + d];
        float uu  = ucv  [idx*DI + d];
        float Bv  = dbl[idx*96 + DTR + n];
        float Cv  = dbl[idx*96 + DTR + NN + n];
        float du  = dlt * uu;
        h = fmaf(__expf(dlt * A), h, du * Bv);
        float p = h * Cv;
        p += __shfl_xor_sync(0xffffffffu, p, 8);
        p += __shfl_xor_sync(0xffffffffu, p, 4);
        p += __shfl_xor_sync(0xffffffffu, p, 2);
        p += __shfl_xor_sync(0xffffffffu, p, 1);
        if (n == 0) {
            float r  = ur[idx*(2*DI) + DI + d];
            float sr = r / (1.f + __expf(-r));
            yg[idx*DI + d] = (p + uu * Dd) * sr;
        }
    }
}

// ---------------------------------------------------------------------------
// Launch
// ---------------------------------------------------------------------------
extern "C" void kernel_launch(void* const* d_in, const int* in_sizes, int n_in,
                              void* d_out, int out_size)
{
    const int*   x     = (const int*)  d_in[0];
    const int*   qid   = (const int*)  d_in[1];
    const float* emb   = (const float*)d_in[2];
    const float* qc    = (const float*)d_in[3];
    const float* ln0g  = (const float*)d_in[4];
    const float* ln0b  = (const float*)d_in[5];
    const float* inw   = (const float*)d_in[6];
    const float* convw = (const float*)d_in[7];
    const float* convb = (const float*)d_in[8];
    const float* xpw   = (const float*)d_in[9];
    const float* dtw   = (const float*)d_in[10];
    const float* dtb   = (const float*)d_in[11];
    const float* alog  = (const float*)d_in[12];
    const float* dpar  = (const float*)d_in[13];
    const float* outw  = (const float*)d_in[14];
    const float* ln1g  = (const float*)d_in[15];
    const float* ln1b  = (const float*)d_in[16];
    const float* fcw   = (const float*)d_in[17];
    const float* fcb   = (const float*)d_in[18];
    float* out = (float*)d_out;

    float *item, *ur, *ucv, *dbl, *delta, *yg, *hout, *lnout;
    cudaGetSymbolAddress((void**)&item,  g_item);
    cudaGetSymbolAddress((void**)&ur,    g_ur);
    cudaGetSymbolAddress((void**)&ucv,   g_ucv);
    cudaGetSymbolAddress((void**)&dbl,   g_dbl);
    cudaGetSymbolAddress((void**)&delta, g_delta);
    cudaGetSymbolAddress((void**)&yg,    g_yg);
    cudaGetSymbolAddress((void**)&hout,  g_hout);
    cudaGetSymbolAddress((void**)&lnout, g_lnout);

    const int SMEM = 2 * 2 * TILE_F * 4;   // 73,728 B
    cudaFuncSetAttribute(gemm_mma<0>, cudaFuncAttributeMaxDynamicSharedMemorySize, SMEM);
    cudaFuncSetAttribute(gemm_mma<1>, cudaFuncAttributeMaxDynamicSharedMemorySize, SMEM);
    cudaFuncSetAttribute(gemm_mma<2>, cudaFuncAttributeMaxDynamicSharedMemorySize, SMEM);

    // 1) embed + concat + LN0
    embed_ln0_kernel<<<BL, 256>>>(x, qid, emb, qc, ln0g, ln0b, item);

    // 2) in_proj
    gemm_mma<0><<<dim3(2*DI/128, BL/128), 256, SMEM>>>(item, DM, inw, DM, ur, 2*DI,
                                                       BL, 2*DI, DM, nullptr);

    // 3) depthwise conv + SiLU
    conv_silu_kernel<<<dim3(DI/256, LL/CONV_CHUNK, BB), 256>>>(ur, convw, convb, ucv);

    // 4) x_proj
    gemm_mma<0><<<dim3(1, BL/128), 256, SMEM>>>(ucv, DI, xpw, DI, dbl, 96,
                                                BL, 96, DI, nullptr);

    // 5) dt_proj + softplus
    gemm_mma<1><<<dim3(DI/128, BL/128), 256, SMEM>>>(dbl, 96, dtw, DTR, delta, DI,
                                                     BL, DI, DTR, dtb);

    // 6) selective scan + gate
    scan_kernel<<<dim3(DI/16, BB), 256>>>(delta, ucv, dbl, ur, alog, dpar, yg);

    // 7) out_proj
    gemm_mma<0><<<dim3(DM/128, BL/128), 256, SMEM>>>(yg, DI, outw, DI, hout, DM,
                                                     BL, DM, DI, nullptr);

    // 8) residual + LN1
    add_ln_kernel<<<BL, 256>>>(hout, item, ln1g, ln1b, lnout);

    // 9) fc + bias + sigmoid
    gemm_mma<2><<<dim3((QUES+127)/128, BL/128), 256, SMEM>>>(lnout, DM, fcw, DM, out, QUES,
                                                             BL, QUES, DM, fcb);
}